// round 5
// baseline (speedup 1.0000x reference)
#include <cuda_runtime.h>
#include <cuda_fp16.h>
#include <cstdint>

// ---------------------------------------------------------------------------
// RNNT joiner, two-pass:
//   pass 1: Ah[m][d] = fp16(relu(src[b,t,d] + tgt[b,u,d]))
//   pass 2: out = Ah @ Wh^T + bias  (M=65536, N=1024, K=1024, HMMA fp16)
// R4 ncu: L1TEX 61.5% (top pipe), tensor 38.2% -> smem-fragment-traffic bound.
// Fix: 64x64 warp tiles (4 warps, 128 thr, CTA 128x128x32) cut LDSM bytes/FLOP
// from 0.047 to 0.031 and keep 2 CTAs/SM.
// ---------------------------------------------------------------------------

#define B_ 4
#define T_ 256
#define U_ 64
#define D_ 1024
#define V_ 1024
#define M_ (B_ * T_ * U_)

#define TILE_M 128
#define TILE_N 128
#define TILE_K 32
#define KITERS (D_ / TILE_K) /* 32 */
#define NTHREADS 128
#define NSTAGE 4

#define PITCH 80                      /* 64B row + 16B pad: conflict-free ldmatrix */
#define STAGE_BYTES (128 * PITCH)     /* 10240 */
#define SMEM_DYN (2 * NSTAGE * STAGE_BYTES) /* A[4] + B[4] = 81920 */

__device__ __forceinline__ uint32_t smem_u32(const void* p) {
    uint32_t a;
    asm("{ .reg .u64 t; cvta.to.shared.u64 t, %1; cvt.u32.u64 %0, t; }" : "=r"(a) : "l"(p));
    return a;
}

__device__ __forceinline__ void cp16(uint32_t saddr, const void* g) {
    asm volatile("cp.async.cg.shared.global [%0], [%1], 16;" :: "r"(saddr), "l"(g) : "memory");
}
#define CP_COMMIT() asm volatile("cp.async.commit_group;" ::: "memory")
#define CP_WAIT(n)  asm volatile("cp.async.wait_group %0;" :: "n"(n) : "memory")

__device__ __forceinline__ void ldsm_x4(uint32_t (&r)[4], uint32_t addr) {
    asm volatile("ldmatrix.sync.aligned.m8n8.x4.shared.b16 {%0,%1,%2,%3}, [%4];"
                 : "=r"(r[0]), "=r"(r[1]), "=r"(r[2]), "=r"(r[3]) : "r"(addr));
}

__device__ __forceinline__ void mma16816(float (&d)[4], const uint32_t (&a)[4],
                                         uint32_t b0, uint32_t b1) {
    asm volatile(
        "mma.sync.aligned.m16n8k16.row.col.f32.f16.f16.f32 "
        "{%0,%1,%2,%3}, {%4,%5,%6,%7}, {%8,%9}, {%0,%1,%2,%3};"
        : "+f"(d[0]), "+f"(d[1]), "+f"(d[2]), "+f"(d[3])
        : "r"(a[0]), "r"(a[1]), "r"(a[2]), "r"(a[3]), "r"(b0), "r"(b1));
}

__device__ __forceinline__ uint32_t h2u(__half2 h) { return *reinterpret_cast<uint32_t*>(&h); }

// Static scratch: W in fp16 (2 MB) and the materialized A operand (128 MB fp16).
__device__ __align__(16) __half g_Wh[(size_t)V_ * D_];
__device__ __align__(16) __half g_Ah[(size_t)M_ * D_];

// convert W + write the appended lengths tail in one aux kernel
__global__ void prep_kernel(const float* __restrict__ W,
                            const int* __restrict__ sl, const int* __restrict__ tl,
                            float* __restrict__ tail_out, int ntail) {
    int i = blockIdx.x * blockDim.x + threadIdx.x;  // over V*D/4
    float4 v = reinterpret_cast<const float4*>(W)[i];
    __half2* dst = reinterpret_cast<__half2*>(g_Wh);
    dst[2 * i + 0] = __floats2half2_rn(v.x, v.y);
    dst[2 * i + 1] = __floats2half2_rn(v.z, v.w);
    if (blockIdx.x == 0 && threadIdx.x < (unsigned)ntail) {
        int k = threadIdx.x;
        int val = (k < B_) ? sl[k] : ((k < 2 * B_) ? tl[k - B_] : 0);
        tail_out[k] = (float)val;
    }
}

// pass 1: Ah = fp16(relu(src+tgt)); 8 elements per thread
__global__ void __launch_bounds__(256) build_A(const float* __restrict__ src,
                                               const float* __restrict__ tgt) {
    size_t i = (size_t)blockIdx.x * blockDim.x + threadIdx.x;  // over M*D/8
    int dc = (int)(i & (D_ / 8 - 1)) * 8;
    size_t row = i >> 7;
    int u = (int)(row & (U_ - 1));
    int t = (int)((row >> 6) & (T_ - 1));
    int b = (int)(row >> 14);
    const float4* sp = reinterpret_cast<const float4*>(src + ((size_t)(b * T_ + t)) * D_ + dc);
    const float4* tp = reinterpret_cast<const float4*>(tgt + ((size_t)(b * U_ + u)) * D_ + dc);
    float4 s0 = sp[0], s1 = sp[1];
    float4 g0 = tp[0], g1 = tp[1];
    __half2 h0 = __floats2half2_rn(fmaxf(s0.x + g0.x, 0.f), fmaxf(s0.y + g0.y, 0.f));
    __half2 h1 = __floats2half2_rn(fmaxf(s0.z + g0.z, 0.f), fmaxf(s0.w + g0.w, 0.f));
    __half2 h2 = __floats2half2_rn(fmaxf(s1.x + g1.x, 0.f), fmaxf(s1.y + g1.y, 0.f));
    __half2 h3 = __floats2half2_rn(fmaxf(s1.z + g1.z, 0.f), fmaxf(s1.w + g1.w, 0.f));
    *reinterpret_cast<uint4*>(g_Ah + row * D_ + dc) =
        make_uint4(h2u(h0), h2u(h1), h2u(h2), h2u(h3));
}

__global__ void __launch_bounds__(NTHREADS, 2) joiner_gemm(
    const float* __restrict__ bias, float* __restrict__ out) {
    extern __shared__ __align__(128) char smem[];
    const uint32_t A0 = smem_u32(smem);
    const uint32_t Bb0 = A0 + NSTAGE * STAGE_BYTES;

    const int tid = threadIdx.x;
    const int wid = tid >> 5, lane = tid & 31;
    const int nt = blockIdx.x;   // 0..7   (nt-fast: 8 CTAs share one A tile in L2)
    const int mt = blockIdx.y;   // 0..511

    // ---- load-role: thread -> one row (0..127), 4 x 16B segments ----
    const __half* arow = g_Ah + ((size_t)(mt * TILE_M + tid)) * D_;
    const __half* wrow = g_Wh + ((size_t)(nt * TILE_N + tid)) * D_;
    const uint32_t fill_off = (uint32_t)tid * PITCH;

    // ---- mma-role: 4 warps = 2m x 2n, warp tile 64x64 ----
    const int wm = wid & 1;
    const int wn = wid >> 1;
    const int m0w = wm * 64;
    const int n0w = wn * 64;
    // A frag (mi-th 16-row block): rows m0w+mi*16+(lane&15), k-half (lane>>4)
    const uint32_t a_ld_off = (uint32_t)(m0w + (lane & 15)) * PITCH + (lane >> 4) * 16;
    // B frag (p-th 16-row block): rows n0w+p*16+(lane&7)+((lane&16)>>1), k-half ((lane>>3)&1)
    const uint32_t b_ld_off =
        (uint32_t)(n0w + (lane & 7) + ((lane & 16) >> 1)) * PITCH + ((lane >> 3) & 1) * 16;

    float acc[4][8][4];
#pragma unroll
    for (int mi = 0; mi < 4; mi++)
#pragma unroll
        for (int ni = 0; ni < 8; ni++)
#pragma unroll
            for (int q = 0; q < 4; q++) acc[mi][ni][q] = 0.f;

    auto loadStage = [&](int s, int kt) {
        const __half* ga = arow + kt * TILE_K;
        const __half* gb = wrow + kt * TILE_K;
        uint32_t da = A0 + s * STAGE_BYTES + fill_off;
        uint32_t db = Bb0 + s * STAGE_BYTES + fill_off;
#pragma unroll
        for (int seg = 0; seg < 4; seg++) {
            cp16(da + seg * 16, ga + seg * 8);
            cp16(db + seg * 16, gb + seg * 8);
        }
    };

    // prologue: stages 0,1,2 in flight
#pragma unroll
    for (int s = 0; s < NSTAGE - 1; s++) {
        loadStage(s, s);
        CP_COMMIT();
    }

#pragma unroll 1
    for (int kt = 0; kt < KITERS; kt++) {
        const int cur = kt & (NSTAGE - 1);
        CP_WAIT(2);          // stage `cur` complete
        __syncthreads();
        if (kt + NSTAGE - 1 < KITERS)
            loadStage((kt + NSTAGE - 1) & (NSTAGE - 1), kt + NSTAGE - 1);
        CP_COMMIT();

        const uint32_t Ab = A0 + cur * STAGE_BYTES;
        const uint32_t Bt = Bb0 + cur * STAGE_BYTES;
#pragma unroll
        for (int k16 = 0; k16 < 2; k16++) {
            const uint32_t kb = k16 * 32;
            uint32_t bfr[4][4];
#pragma unroll
            for (int p = 0; p < 4; p++)
                ldsm_x4(bfr[p], Bt + (uint32_t)(p * 16) * PITCH + b_ld_off + kb);
            uint32_t afr[4][4];
#pragma unroll
            for (int mi = 0; mi < 4; mi++)
                ldsm_x4(afr[mi], Ab + (uint32_t)(mi * 16) * PITCH + a_ld_off + kb);
#pragma unroll
            for (int mi = 0; mi < 4; mi++)
#pragma unroll
                for (int ni = 0; ni < 8; ni++)
                    mma16816(acc[mi][ni], afr[mi], bfr[ni >> 1][(ni & 1) * 2],
                             bfr[ni >> 1][(ni & 1) * 2 + 1]);
        }
    }

    // ---- epilogue: add bias, write fp32 ----
    const int g = lane >> 2;
    const int tig = lane & 3;
    const int gn0 = nt * TILE_N + n0w;
    float2 bb[8];
#pragma unroll
    for (int ni = 0; ni < 8; ni++)
        bb[ni] = *reinterpret_cast<const float2*>(bias + gn0 + ni * 8 + tig * 2);

    const size_t rowbase = (size_t)mt * TILE_M + m0w;
#pragma unroll
    for (int mi = 0; mi < 4; mi++) {
        size_t r0 = rowbase + mi * 16 + g;
        size_t r1 = r0 + 8;
#pragma unroll
        for (int ni = 0; ni < 8; ni++) {
            float* p0 = out + r0 * (size_t)V_ + gn0 + ni * 8 + tig * 2;
            float* p1 = out + r1 * (size_t)V_ + gn0 + ni * 8 + tig * 2;
            *reinterpret_cast<float2*>(p0) =
                make_float2(acc[mi][ni][0] + bb[ni].x, acc[mi][ni][1] + bb[ni].y);
            *reinterpret_cast<float2*>(p1) =
                make_float2(acc[mi][ni][2] + bb[ni].x, acc[mi][ni][3] + bb[ni].y);
        }
    }
}

extern "C" void kernel_launch(void* const* d_in, const int* in_sizes, int n_in,
                              void* d_out, int out_size) {
    const float* src  = (const float*)d_in[0];
    const int*   slen = (const int*)d_in[1];
    const float* tgt  = (const float*)d_in[2];
    const int*   tlen = (const int*)d_in[3];
    const float* W    = (const float*)d_in[4];
    const float* bias = (const float*)d_in[5];
    float* out = (float*)d_out;

    long long main_elems = (long long)M_ * V_;
    int ntail = 0;
    if ((long long)out_size > main_elems) {
        ntail = (int)((long long)out_size - main_elems);
        if (ntail > 32) ntail = 32;
    }
    prep_kernel<<<(V_ * D_ / 4) / 256, 256>>>(W, slen, tlen, out + main_elems, ntail);
    build_A<<<((size_t)M_ * D_ / 8) / 256, 256>>>(src, tgt);

    cudaFuncSetAttribute(joiner_gemm, cudaFuncAttributeMaxDynamicSharedMemorySize, SMEM_DYN);
    dim3 grid(V_ / TILE_N, M_ / TILE_M);  // (8, 512) nt-fast
    joiner_gemm<<<grid, NTHREADS, SMEM_DYN>>>(bias, out);
}

// round 6
// speedup vs baseline: 1.9647x; 1.9647x over previous
#include <cuda_runtime.h>
#include <cuda_fp16.h>
#include <cstdint>

// ---------------------------------------------------------------------------
// RNNT joiner, fused single-pass GEMM at the mma.sync issue floor (~504us):
//   out[m,v] = sum_d relu(src[b,t,d]+tgt[b,u,d]) * W[v,d] + bias[v]
// M=65536, N=1024, K=1024. A tile (128 rows = 2 src rows x 64 tgt rows) built
// in-kernel in fp16 (HADD2/HMAX2) from fp16-preconverted src/tgt staged via
// cp.async. GEMM core identical to the proven floor kernel (R3): CTA 128x128x32,
// 256 thr, 8 warps (4m x 2n, warp 32x64), 4-stage cp.async, 2 CTAs/SM.
// ---------------------------------------------------------------------------

#define B_ 4
#define T_ 256
#define U_ 64
#define D_ 1024
#define V_ 1024
#define M_ (B_ * T_ * U_)

#define TILE_M 128
#define TILE_N 128
#define TILE_K 32
#define KITERS (D_ / TILE_K) /* 32 */
#define NTHREADS 256
#define NSTAGE 4

#define PITCH 80                      /* 64B row + 16B pad: conflict-free-ish */
#define STAGE_BYTES (128 * PITCH)     /* 10240 */
#define TGT_STAGE (64 * PITCH)        /* 5120: 64 fp16 rows x 64B */
#define SRC_STAGE 256                 /* 2 fp16 rows x 80B, padded */

// smem: B[4] | A[2] | tgt[4] | src[4]
#define OFF_B 0
#define OFF_A (NSTAGE * STAGE_BYTES)            /* 40960 */
#define OFF_T (OFF_A + 2 * STAGE_BYTES)         /* 61440 */
#define OFF_S (OFF_T + NSTAGE * TGT_STAGE)      /* 81920 */
#define SMEM_DYN (OFF_S + NSTAGE * SRC_STAGE)   /* 82944 -> 2 CTAs/SM */

__device__ __forceinline__ uint32_t smem_u32(const void* p) {
    uint32_t a;
    asm("{ .reg .u64 t; cvta.to.shared.u64 t, %1; cvt.u32.u64 %0, t; }" : "=r"(a) : "l"(p));
    return a;
}

__device__ __forceinline__ void cp16(uint32_t saddr, const void* g) {
    asm volatile("cp.async.cg.shared.global [%0], [%1], 16;" :: "r"(saddr), "l"(g) : "memory");
}
#define CP_COMMIT() asm volatile("cp.async.commit_group;" ::: "memory")
#define CP_WAIT(n)  asm volatile("cp.async.wait_group %0;" :: "n"(n) : "memory")

__device__ __forceinline__ void ldsm_x4(uint32_t (&r)[4], uint32_t addr) {
    asm volatile("ldmatrix.sync.aligned.m8n8.x4.shared.b16 {%0,%1,%2,%3}, [%4];"
                 : "=r"(r[0]), "=r"(r[1]), "=r"(r[2]), "=r"(r[3]) : "r"(addr));
}

__device__ __forceinline__ void mma16816(float (&d)[4], const uint32_t (&a)[4],
                                         uint32_t b0, uint32_t b1) {
    asm volatile(
        "mma.sync.aligned.m16n8k16.row.col.f32.f16.f16.f32 "
        "{%0,%1,%2,%3}, {%4,%5,%6,%7}, {%8,%9}, {%0,%1,%2,%3};"
        : "+f"(d[0]), "+f"(d[1]), "+f"(d[2]), "+f"(d[3])
        : "r"(a[0]), "r"(a[1]), "r"(a[2]), "r"(a[3]), "r"(b0), "r"(b1));
}

__device__ __forceinline__ void sts128(uint32_t addr, uint32_t x, uint32_t y,
                                       uint32_t z, uint32_t w) {
    asm volatile("st.shared.v4.b32 [%0], {%1,%2,%3,%4};"
                 :: "r"(addr), "r"(x), "r"(y), "r"(z), "r"(w) : "memory");
}

__device__ __forceinline__ void lds128(uint32_t (&r)[4], uint32_t addr) {
    asm volatile("ld.shared.v4.b32 {%0,%1,%2,%3}, [%4];"
                 : "=r"(r[0]), "=r"(r[1]), "=r"(r[2]), "=r"(r[3]) : "r"(addr));
}

__device__ __forceinline__ uint32_t h2u(__half2 h) { return *reinterpret_cast<uint32_t*>(&h); }
__device__ __forceinline__ __half2 u2h(uint32_t u) { return *reinterpret_cast<__half2*>(&u); }

// Static fp16 scratch: W [V][D] (2MB), src [B*T][D] (2MB), tgt [B*U][D] (0.5MB)
__device__ __align__(16) __half g_Wh[(size_t)V_ * D_];
__device__ __align__(16) __half g_Sh[(size_t)B_ * T_ * D_];
__device__ __align__(16) __half g_Th[(size_t)B_ * U_ * D_];

#define NW (V_ * D_ / 4)        /* 262144 float4 items */
#define NS (B_ * T_ * D_ / 4)   /* 262144 */
#define NT (B_ * U_ * D_ / 4)   /* 65536  */

// One aux kernel: convert W/src/tgt to fp16, write lengths tail.
__global__ void __launch_bounds__(256) prep_kernel(
    const float* __restrict__ W, const float* __restrict__ src,
    const float* __restrict__ tgt,
    const int* __restrict__ sl, const int* __restrict__ tl,
    float* __restrict__ tail_out, int ntail) {
    int i = blockIdx.x * blockDim.x + threadIdx.x;
    const float4* in;
    uint2* out;
    int j;
    if (i < NW)            { in = (const float4*)W;   out = (uint2*)g_Wh; j = i; }
    else if (i < NW + NS)  { in = (const float4*)src; out = (uint2*)g_Sh; j = i - NW; }
    else                   { in = (const float4*)tgt; out = (uint2*)g_Th; j = i - NW - NS; }
    float4 v = in[j];
    uint2 o;
    o.x = h2u(__floats2half2_rn(v.x, v.y));
    o.y = h2u(__floats2half2_rn(v.z, v.w));
    out[j] = o;
    if (blockIdx.x == 0 && threadIdx.x < (unsigned)ntail) {
        int k = threadIdx.x;
        int val = (k < B_) ? sl[k] : ((k < 2 * B_) ? tl[k - B_] : 0);
        tail_out[k] = (float)val;
    }
}

__global__ void __launch_bounds__(NTHREADS, 2) joiner_gemm(
    const float* __restrict__ bias, float* __restrict__ out) {
    extern __shared__ __align__(128) char smem[];
    const uint32_t S0 = smem_u32(smem);

    const int tid = threadIdx.x;
    const int wid = tid >> 5, lane = tid & 31;
    const int nt = blockIdx.x;   // 0..7  (nt-fast: 8 CTAs share src/tgt slices in L2)
    const int mt = blockIdx.y;   // 0..511
    const int b = mt >> 7;
    const int t0 = (mt & 127) * 2;

    // ---- load/build roles: thread -> (row r = tid>>1, half hf = tid&1) ----
    const int r = tid >> 1;
    const int hf = tid & 1;
    const __half* wrow = g_Wh + ((size_t)(nt * TILE_N + r)) * D_ + hf * 16;
    const uint32_t fill_off = (uint32_t)r * PITCH + hf * 32;
    const int t_loc = r >> 6;     // 0..1
    const int u_loc = r & 63;
    const __half* tgtb = g_Th + ((size_t)(b * U_)) * D_;
    const __half* srcb = g_Sh + ((size_t)(b * T_ + t0)) * D_;
    // tgt stage fill: 64 rows x 4 segs = 256 cp16 -> 1 per thread
    const int tg_row = tid >> 2, tg_seg = tid & 3;

    // ---- mma-role mapping (8 warps = 4m x 2n, warp 32x64) ----
    const int wm = wid & 3;
    const int wn = wid >> 2;
    const int m0w = wm * 32;
    const int n0w = wn * 64;
    const uint32_t a_ld_off = (uint32_t)(m0w + (lane & 15)) * PITCH + (lane >> 4) * 16;
    const uint32_t b_ld_off =
        (uint32_t)(n0w + (lane & 7) + ((lane & 16) >> 1)) * PITCH + ((lane >> 3) & 1) * 16;

    float acc[2][8][4];
#pragma unroll
    for (int mi = 0; mi < 2; mi++)
#pragma unroll
        for (int ni = 0; ni < 8; ni++)
#pragma unroll
            for (int q = 0; q < 4; q++) acc[mi][ni][q] = 0.f;

    // cp.async for one k-stage: B tile (8KB) + tgt slice (4KB) + src slice (128B)
    auto loadStage = [&](int s, int kt) {
        const int k0 = kt * TILE_K;
        uint32_t db = S0 + OFF_B + s * STAGE_BYTES + fill_off;
        const __half* gb = wrow + k0;
        cp16(db, gb);
        cp16(db + 16, gb + 8);
        cp16(S0 + OFF_T + s * TGT_STAGE + (uint32_t)tg_row * PITCH + tg_seg * 16,
             tgtb + (size_t)tg_row * D_ + k0 + tg_seg * 8);
        if (tid < 8) {
            int sr = tid >> 2, seg = tid & 3;
            cp16(S0 + OFF_S + s * SRC_STAGE + (uint32_t)sr * PITCH + seg * 16,
                 srcb + (size_t)sr * D_ + k0 + seg * 8);
        }
    };

    // build fp16 A tile for stage kt (staging slot kt&3 -> A buffer kt&1)
    auto buildA = [&](int kt) {
        const int s = kt & (NSTAGE - 1);
        const uint32_t sp = S0 + OFF_S + s * SRC_STAGE + (uint32_t)t_loc * PITCH + hf * 32;
        const uint32_t tp = S0 + OFF_T + s * TGT_STAGE + (uint32_t)u_loc * PITCH + hf * 32;
        uint32_t sv[4], sv2[4], tv[4], tv2[4];
        lds128(sv, sp);
        lds128(sv2, sp + 16);
        lds128(tv, tp);
        lds128(tv2, tp + 16);
        const __half2 z = __float2half2_rn(0.f);
        uint32_t o[8];
#pragma unroll
        for (int q = 0; q < 4; q++) {
            o[q]     = h2u(__hmax2(__hadd2(u2h(sv[q]),  u2h(tv[q])),  z));
            o[q + 4] = h2u(__hmax2(__hadd2(u2h(sv2[q]), u2h(tv2[q])), z));
        }
        uint32_t a = S0 + OFF_A + (kt & 1) * STAGE_BYTES + fill_off;
        sts128(a,      o[0], o[1], o[2], o[3]);
        sts128(a + 16, o[4], o[5], o[6], o[7]);
    };

    // ---- prologue: stages 0,1,2 in flight; build A(0) ----
#pragma unroll
    for (int s = 0; s < NSTAGE - 1; s++) {
        loadStage(s, s);
        CP_COMMIT();
    }
    CP_WAIT(2);          // stage 0 complete
    __syncthreads();
    buildA(0);

#pragma unroll 1
    for (int kt = 0; kt < KITERS; kt++) {
        const int cur = kt & (NSTAGE - 1);
        CP_WAIT(1);      // stage kt+1 complete (only newest group pending)
        __syncthreads(); // A(kt) visible; stage (kt+3)&3 slot reusable
        if (kt + NSTAGE - 1 < KITERS)
            loadStage((kt + NSTAGE - 1) & (NSTAGE - 1), kt + NSTAGE - 1);
        CP_COMMIT();     // possibly-empty group keeps wait counts uniform
        if (kt + 1 < KITERS) buildA(kt + 1);

        const uint32_t Ab = S0 + OFF_A + (kt & 1) * STAGE_BYTES;
        const uint32_t Bt = S0 + OFF_B + cur * STAGE_BYTES;
#pragma unroll
        for (int k16 = 0; k16 < 2; k16++) {
            const uint32_t kb = k16 * 32;
            uint32_t bfr[4][4];
#pragma unroll
            for (int p = 0; p < 4; p++)
                ldsm_x4(bfr[p], Bt + (uint32_t)(p * 16) * PITCH + b_ld_off + kb);
#pragma unroll
            for (int mi = 0; mi < 2; mi++) {
                uint32_t af[4];
                ldsm_x4(af, Ab + a_ld_off + (uint32_t)(mi * 16) * PITCH + kb);
#pragma unroll
                for (int ni = 0; ni < 8; ni++)
                    mma16816(acc[mi][ni], af, bfr[ni >> 1][(ni & 1) * 2],
                             bfr[ni >> 1][(ni & 1) * 2 + 1]);
            }
        }
    }

    // ---- epilogue: add bias, write fp32 ----
    const int g = lane >> 2;
    const int tig = lane & 3;
    const int gn0 = nt * TILE_N + n0w;
    float2 bb[8];
#pragma unroll
    for (int ni = 0; ni < 8; ni++)
        bb[ni] = *reinterpret_cast<const float2*>(bias + gn0 + ni * 8 + tig * 2);

    const size_t rowbase = (size_t)mt * TILE_M + m0w;
#pragma unroll
    for (int mi = 0; mi < 2; mi++) {
        size_t r0 = rowbase + mi * 16 + g;
        size_t r1 = r0 + 8;
#pragma unroll
        for (int ni = 0; ni < 8; ni++) {
            float* p0 = out + r0 * (size_t)V_ + gn0 + ni * 8 + tig * 2;
            float* p1 = out + r1 * (size_t)V_ + gn0 + ni * 8 + tig * 2;
            *reinterpret_cast<float2*>(p0) =
                make_float2(acc[mi][ni][0] + bb[ni].x, acc[mi][ni][1] + bb[ni].y);
            *reinterpret_cast<float2*>(p1) =
                make_float2(acc[mi][ni][2] + bb[ni].x, acc[mi][ni][3] + bb[ni].y);
        }
    }
}

extern "C" void kernel_launch(void* const* d_in, const int* in_sizes, int n_in,
                              void* d_out, int out_size) {
    const float* src  = (const float*)d_in[0];
    const int*   slen = (const int*)d_in[1];
    const float* tgt  = (const float*)d_in[2];
    const int*   tlen = (const int*)d_in[3];
    const float* W    = (const float*)d_in[4];
    const float* bias = (const float*)d_in[5];
    float* out = (float*)d_out;

    long long main_elems = (long long)M_ * V_;
    int ntail = 0;
    if ((long long)out_size > main_elems) {
        ntail = (int)((long long)out_size - main_elems);
        if (ntail > 32) ntail = 32;
    }
    prep_kernel<<<(NW + NS + NT) / 256, 256>>>(W, src, tgt, slen, tlen,
                                               out + main_elems, ntail);

    cudaFuncSetAttribute(joiner_gemm, cudaFuncAttributeMaxDynamicSharedMemorySize, SMEM_DYN);
    dim3 grid(V_ / TILE_N, M_ / TILE_M);  // (8, 512) nt-fast
    joiner_gemm<<<grid, NTHREADS, SMEM_DYN>>>(bias, out);
}

// round 7
// speedup vs baseline: 2.3961x; 1.2195x over previous
#include <cuda_runtime.h>
#include <cuda_fp16.h>
#include <cstdint>

// ---------------------------------------------------------------------------
// RNNT joiner, two-pass:
//   pass 1: Ah[m][d] = fp16(relu(src[b,t,d] + tgt[b,u,d]))
//   pass 2: out = Ah @ Wh^T + bias  (M=65536, N=1024, K=1024, HMMA fp16)
// R6 diagnosis: latency-bound at 16 warps/SM (issue 20%, no pipe saturated).
// Fix: 32 warps/SM -> regs <= 64/thread -> pure GEMM, 512 thr/CTA,
// 16 warps (4m x 4n of 32x32), CTA 128x128x32, 4-stage cp.async, 2 CTAs/SM.
// ---------------------------------------------------------------------------

#define B_ 4
#define T_ 256
#define U_ 64
#define D_ 1024
#define V_ 1024
#define M_ (B_ * T_ * U_)

#define TILE_M 128
#define TILE_N 128
#define TILE_K 32
#define KITERS (D_ / TILE_K) /* 32 */
#define NTHREADS 512
#define NSTAGE 4

#define PITCH 80                      /* 64B row + 16B pad: conflict-free ldmatrix */
#define STAGE_BYTES (128 * PITCH)     /* 10240 */
#define SMEM_DYN (2 * NSTAGE * STAGE_BYTES) /* A[4] + B[4] = 81920 -> 2 CTAs/SM */

__device__ __forceinline__ uint32_t smem_u32(const void* p) {
    uint32_t a;
    asm("{ .reg .u64 t; cvta.to.shared.u64 t, %1; cvt.u32.u64 %0, t; }" : "=r"(a) : "l"(p));
    return a;
}

__device__ __forceinline__ void cp16(uint32_t saddr, const void* g) {
    asm volatile("cp.async.cg.shared.global [%0], [%1], 16;" :: "r"(saddr), "l"(g) : "memory");
}
#define CP_COMMIT() asm volatile("cp.async.commit_group;" ::: "memory")
#define CP_WAIT(n)  asm volatile("cp.async.wait_group %0;" :: "n"(n) : "memory")

__device__ __forceinline__ void ldsm_x4(uint32_t (&r)[4], uint32_t addr) {
    asm volatile("ldmatrix.sync.aligned.m8n8.x4.shared.b16 {%0,%1,%2,%3}, [%4];"
                 : "=r"(r[0]), "=r"(r[1]), "=r"(r[2]), "=r"(r[3]) : "r"(addr));
}

__device__ __forceinline__ void mma16816(float (&d)[4], const uint32_t (&a)[4],
                                         uint32_t b0, uint32_t b1) {
    asm volatile(
        "mma.sync.aligned.m16n8k16.row.col.f32.f16.f16.f32 "
        "{%0,%1,%2,%3}, {%4,%5,%6,%7}, {%8,%9}, {%0,%1,%2,%3};"
        : "+f"(d[0]), "+f"(d[1]), "+f"(d[2]), "+f"(d[3])
        : "r"(a[0]), "r"(a[1]), "r"(a[2]), "r"(a[3]), "r"(b0), "r"(b1));
}

__device__ __forceinline__ uint32_t h2u(__half2 h) { return *reinterpret_cast<uint32_t*>(&h); }

// Static scratch: W in fp16 (2 MB) and the materialized A operand (128 MB fp16).
__device__ __align__(16) __half g_Wh[(size_t)V_ * D_];
__device__ __align__(16) __half g_Ah[(size_t)M_ * D_];

// convert W + write the appended lengths tail
__global__ void __launch_bounds__(256) prep_kernel(
    const float* __restrict__ W,
    const int* __restrict__ sl, const int* __restrict__ tl,
    float* __restrict__ tail_out, int ntail) {
    int i = blockIdx.x * blockDim.x + threadIdx.x;  // over V*D/4
    float4 v = reinterpret_cast<const float4*>(W)[i];
    __half2* dst = reinterpret_cast<__half2*>(g_Wh);
    dst[2 * i + 0] = __floats2half2_rn(v.x, v.y);
    dst[2 * i + 1] = __floats2half2_rn(v.z, v.w);
    if (blockIdx.x == 0 && threadIdx.x < (unsigned)ntail) {
        int k = threadIdx.x;
        int val = (k < B_) ? sl[k] : ((k < 2 * B_) ? tl[k - B_] : 0);
        tail_out[k] = (float)val;
    }
}

// pass 1: Ah = fp16(relu(src+tgt)); 8 elements per thread
__global__ void __launch_bounds__(256) build_A(const float* __restrict__ src,
                                               const float* __restrict__ tgt) {
    size_t i = (size_t)blockIdx.x * blockDim.x + threadIdx.x;  // over M*D/8
    int dc = (int)(i & (D_ / 8 - 1)) * 8;
    size_t row = i >> 7;
    int u = (int)(row & (U_ - 1));
    int t = (int)((row >> 6) & (T_ - 1));
    int b = (int)(row >> 14);
    const float4* sp = reinterpret_cast<const float4*>(src + ((size_t)(b * T_ + t)) * D_ + dc);
    const float4* tp = reinterpret_cast<const float4*>(tgt + ((size_t)(b * U_ + u)) * D_ + dc);
    float4 s0 = sp[0], s1 = sp[1];
    float4 g0 = tp[0], g1 = tp[1];
    __half2 h0 = __floats2half2_rn(fmaxf(s0.x + g0.x, 0.f), fmaxf(s0.y + g0.y, 0.f));
    __half2 h1 = __floats2half2_rn(fmaxf(s0.z + g0.z, 0.f), fmaxf(s0.w + g0.w, 0.f));
    __half2 h2 = __floats2half2_rn(fmaxf(s1.x + g1.x, 0.f), fmaxf(s1.y + g1.y, 0.f));
    __half2 h3 = __floats2half2_rn(fmaxf(s1.z + g1.z, 0.f), fmaxf(s1.w + g1.w, 0.f));
    *reinterpret_cast<uint4*>(g_Ah + row * D_ + dc) =
        make_uint4(h2u(h0), h2u(h1), h2u(h2), h2u(h3));
}

__global__ void __launch_bounds__(NTHREADS, 2) joiner_gemm(
    const float* __restrict__ bias, float* __restrict__ out) {
    extern __shared__ __align__(128) char smem[];
    const uint32_t A0 = smem_u32(smem);
    const uint32_t Bb0 = A0 + NSTAGE * STAGE_BYTES;

    const int tid = threadIdx.x;
    const int wid = tid >> 5, lane = tid & 31;
    const int nt = blockIdx.x;   // 0..7   (nt-fast: 8 CTAs share one A tile in L2)
    const int mt = blockIdx.y;   // 0..511

    // ---- load-role: thread -> (row = tid>>2, seg = tid&3); 1 cp16 per tile ----
    const int lrow = tid >> 2;
    const int lseg = tid & 3;
    const __half* arow = g_Ah + ((size_t)(mt * TILE_M + lrow)) * D_ + lseg * 8;
    const __half* wrow = g_Wh + ((size_t)(nt * TILE_N + lrow)) * D_ + lseg * 8;
    const uint32_t fill_off = (uint32_t)lrow * PITCH + lseg * 16;

    // ---- mma-role: 16 warps = 4m x 4n, warp tile 32x32 ----
    const int m0w = (wid & 3) * 32;
    const int n0w = (wid >> 2) * 32;
    const uint32_t a_ld_off = (uint32_t)(m0w + (lane & 15)) * PITCH + (lane >> 4) * 16;
    const uint32_t b_ld_off =
        (uint32_t)(n0w + (lane & 7) + ((lane & 16) >> 1)) * PITCH + ((lane >> 3) & 1) * 16;

    float acc[2][4][4];
#pragma unroll
    for (int mi = 0; mi < 2; mi++)
#pragma unroll
        for (int ni = 0; ni < 4; ni++)
#pragma unroll
            for (int q = 0; q < 4; q++) acc[mi][ni][q] = 0.f;

    auto loadStage = [&](int s, int kt) {
        cp16(A0 + s * STAGE_BYTES + fill_off, arow + kt * TILE_K);
        cp16(Bb0 + s * STAGE_BYTES + fill_off, wrow + kt * TILE_K);
    };

    // prologue: stages 0,1,2 in flight
#pragma unroll
    for (int s = 0; s < NSTAGE - 1; s++) {
        loadStage(s, s);
        CP_COMMIT();
    }

#pragma unroll 1
    for (int kt = 0; kt < KITERS; kt++) {
        const int cur = kt & (NSTAGE - 1);
        CP_WAIT(2);          // stage `cur` complete
        __syncthreads();
        if (kt + NSTAGE - 1 < KITERS)
            loadStage((kt + NSTAGE - 1) & (NSTAGE - 1), kt + NSTAGE - 1);
        CP_COMMIT();

        const uint32_t Ab = A0 + cur * STAGE_BYTES;
        const uint32_t Bt = Bb0 + cur * STAGE_BYTES;
#pragma unroll
        for (int k16 = 0; k16 < 2; k16++) {
            const uint32_t kb = k16 * 32;
            uint32_t bfr[2][4];
            ldsm_x4(bfr[0], Bt + b_ld_off + kb);
            ldsm_x4(bfr[1], Bt + 16u * PITCH + b_ld_off + kb);
            uint32_t afr[2][4];
            ldsm_x4(afr[0], Ab + a_ld_off + kb);
            ldsm_x4(afr[1], Ab + 16u * PITCH + a_ld_off + kb);
#pragma unroll
            for (int mi = 0; mi < 2; mi++)
#pragma unroll
                for (int ni = 0; ni < 4; ni++)
                    mma16816(acc[mi][ni], afr[mi], bfr[ni >> 1][(ni & 1) * 2],
                             bfr[ni >> 1][(ni & 1) * 2 + 1]);
        }
    }

    // ---- epilogue: add bias, write fp32 ----
    const int g = lane >> 2;
    const int tig = lane & 3;
    const int gn0 = nt * TILE_N + n0w;
    float2 bb[4];
#pragma unroll
    for (int ni = 0; ni < 4; ni++)
        bb[ni] = *reinterpret_cast<const float2*>(bias + gn0 + ni * 8 + tig * 2);

    const size_t rowbase = (size_t)mt * TILE_M + m0w;
#pragma unroll
    for (int mi = 0; mi < 2; mi++) {
        size_t r0 = rowbase + mi * 16 + g;
        size_t r1 = r0 + 8;
#pragma unroll
        for (int ni = 0; ni < 4; ni++) {
            float* p0 = out + r0 * (size_t)V_ + gn0 + ni * 8 + tig * 2;
            float* p1 = out + r1 * (size_t)V_ + gn0 + ni * 8 + tig * 2;
            *reinterpret_cast<float2*>(p0) =
                make_float2(acc[mi][ni][0] + bb[ni].x, acc[mi][ni][1] + bb[ni].y);
            *reinterpret_cast<float2*>(p1) =
                make_float2(acc[mi][ni][2] + bb[ni].x, acc[mi][ni][3] + bb[ni].y);
        }
    }
}

extern "C" void kernel_launch(void* const* d_in, const int* in_sizes, int n_in,
                              void* d_out, int out_size) {
    const float* src  = (const float*)d_in[0];
    const int*   slen = (const int*)d_in[1];
    const float* tgt  = (const float*)d_in[2];
    const int*   tlen = (const int*)d_in[3];
    const float* W    = (const float*)d_in[4];
    const float* bias = (const float*)d_in[5];
    float* out = (float*)d_out;

    long long main_elems = (long long)M_ * V_;
    int ntail = 0;
    if ((long long)out_size > main_elems) {
        ntail = (int)((long long)out_size - main_elems);
        if (ntail > 32) ntail = 32;
    }
    prep_kernel<<<(V_ * D_ / 4) / 256, 256>>>(W, slen, tlen, out + main_elems, ntail);
    build_A<<<((size_t)M_ * D_ / 8) / 256, 256>>>(src, tgt);

    cudaFuncSetAttribute(joiner_gemm, cudaFuncAttributeMaxDynamicSharedMemorySize, SMEM_DYN);
    dim3 grid(V_ / TILE_N, M_ / TILE_M);  // (8, 512) nt-fast
    joiner_gemm<<<grid, NTHREADS, SMEM_DYN>>>(bias, out);
}